// round 10
// baseline (speedup 1.0000x reference)
#include <cuda_runtime.h>
#include <cuda_fp16.h>

#define USER_NUM 100000
#define ITEM_NUM 50000
#define NTOT     (USER_NUM + ITEM_NUM)     // 150000
#define EMB      64
#define NNZ      3000000
#define EPS      0.1f
#define NELEM    (NTOT * EMB)              // 9,600,000
#define NBLK     ((NTOT + 1023) / 1024)    // 147 scan blocks

// ---- static scratch (referenced ONLY in device code; zero-init at load) ----
__device__ __half g_halfA[NELEM];          // fp16 ego0 (gather source, layer 0)
__device__ __half g_halfB[NELEM];          // fp16 e1
__device__ __half g_halfC[NELEM];          // fp16 e2
__device__ int    g_cnt[NTOT];             // zero at entry (scan1 self-cleans)
__device__ int    g_row_ptr[NTOT + 1];
__device__ int    g_cursor[NTOT];
__device__ int    g_blocksum[NBLK];
__device__ float2 g_pair[NNZ];             // dense {val, col} grouped by row

// ---- fp16 helpers ----------------------------------------------------------
__device__ __forceinline__ float4 ldh4(const __half* p) {
    uint2 u = *(const uint2*)p;
    __half2 h0 = *reinterpret_cast<__half2*>(&u.x);
    __half2 h1 = *reinterpret_cast<__half2*>(&u.y);
    float2 f0 = __half22float2(h0);
    float2 f1 = __half22float2(h1);
    return make_float4(f0.x, f0.y, f1.x, f1.y);
}
__device__ __forceinline__ void sth4(__half* p, float4 v) {
    __half2 h0 = __floats2half2_rn(v.x, v.y);
    __half2 h1 = __floats2half2_rn(v.z, v.w);
    uint2 u;
    u.x = *reinterpret_cast<unsigned*>(&h0);
    u.y = *reinterpret_cast<unsigned*>(&h1);
    *(uint2*)p = u;
}

// ---------------------------------------------------------------------------
// fused init + histogram: halfA = fp16(concat(user,item)); cnt[rows[i]]++
// ---------------------------------------------------------------------------
__global__ void init_hist_kernel(const float* __restrict__ ue,
                                 const float* __restrict__ ie,
                                 const int*   __restrict__ rows) {
    int idx = blockIdx.x * blockDim.x + threadIdx.x;
    if (idx == 0) g_row_ptr[NTOT] = NNZ;
    if (idx < NELEM / 4) {
        float4 v;
        if (idx < USER_NUM * EMB / 4) v = ((const float4*)ue)[idx];
        else                          v = ((const float4*)ie)[idx - USER_NUM * EMB / 4];
        sth4(g_halfA + (long long)idx * 4, v);
    }
    if (idx < NNZ) atomicAdd(&g_cnt[rows[idx]], 1);        // result unused -> RED
}

// ---------------------------------------------------------------------------
// CSR build: per-block scan (self-cleaning cnt) -> blockoff apply -> scatter
// ---------------------------------------------------------------------------
__global__ void scan1_kernel() {                 // per-1024-block exclusive scan
    __shared__ int sh[1024];
    int i = blockIdx.x * 1024 + threadIdx.x;
    int v = (i < NTOT) ? g_cnt[i] : 0;
    if (i < NTOT) g_cnt[i] = 0;                  // self-clean for next replay
    sh[threadIdx.x] = v;
    __syncthreads();
    #pragma unroll
    for (int o = 1; o < 1024; o <<= 1) {
        int t = (threadIdx.x >= o) ? sh[threadIdx.x - o] : 0;
        __syncthreads();
        sh[threadIdx.x] += t;
        __syncthreads();
    }
    if (i < NTOT) g_row_ptr[i] = sh[threadIdx.x] - v;      // exclusive within block
    if (threadIdx.x == 1023) g_blocksum[blockIdx.x] = sh[1023];
}

__global__ void scan23_kernel() {                // blockoff reduce + apply + cursors
    __shared__ int sh[256];
    int i    = blockIdx.x * 256 + threadIdx.x;
    int sblk = (blockIdx.x * 256) >> 10;
    int t    = threadIdx.x;
    sh[t] = (t < NBLK && t < sblk) ? g_blocksum[t] : 0;
    __syncthreads();
    #pragma unroll
    for (int o = 128; o; o >>= 1) {
        if (t < o) sh[t] += sh[t + o];
        __syncthreads();
    }
    int off = sh[0];
    if (i >= NTOT) return;
    int v = g_row_ptr[i] + off;
    g_row_ptr[i] = v;
    g_cursor[i]  = v;
}

__global__ void scatter_kernel(const float* __restrict__ vals,
                               const int* __restrict__ rows,
                               const int* __restrict__ cols) {
    int i = blockIdx.x * blockDim.x + threadIdx.x;
    if (i >= NNZ) return;
    int r = rows[i];
    int pos = atomicAdd(&g_cursor[r], 1);
    g_pair[pos] = make_float2(vals[i], __int_as_float(cols[i]));
}

// ---------------------------------------------------------------------------
// Fused layer: gather-SpMM (CSR, half-warp per row, fp16 8B gather, fp32 accum)
//   unroll-8, float4 pair loads (streaming), sign-noise perturb, layer2 -> out.
// ---------------------------------------------------------------------------
__device__ __forceinline__ float sgn(float x) {
    return (x > 0.f) ? 1.f : ((x < 0.f) ? -1.f : 0.f);
}

// L = 0: halfA -> halfB.  L = 1: halfB -> halfC.  L = 2: halfC -> averaged out.
template <int L>
__global__ void __launch_bounds__(256) layer_kernel(const float* __restrict__ noise_k,
                                                    const float* __restrict__ ue,
                                                    const float* __restrict__ ie,
                                                    float* __restrict__ out) {
    const __half* __restrict__ egoIn = (L == 0) ? g_halfA : ((L == 1) ? g_halfB : g_halfC);

    int hw = (blockIdx.x * blockDim.x + threadIdx.x) >> 4;  // half-warp = row
    int l  = threadIdx.x & 15;                              // 4-elem slice
    if (hw >= NTOT) return;

    int beg = g_row_ptr[hw];
    int end = g_row_ptr[hw + 1];

    float4 a = make_float4(0.f, 0.f, 0.f, 0.f);

    int j = beg;
    // peel to 16B-align the pair pointer (float2 array -> even index)
    if ((j & 1) && j < end) {
        float2 p = __ldcs(&g_pair[j]);
        float4 x = ldh4(egoIn + (long long)__float_as_int(p.y) * EMB + 4 * l);
        a.x += p.x * x.x; a.y += p.x * x.y; a.z += p.x * x.z; a.w += p.x * x.w;
        ++j;
    }
    // unroll-8: 4 x LDG.128 pair loads (streaming) + 8 gathers in flight
    for (; j + 8 <= end; j += 8) {
        const float4* pr4 = (const float4*)(g_pair + j);
        float4 q0 = __ldcs(pr4 + 0);
        float4 q1 = __ldcs(pr4 + 1);
        float4 q2 = __ldcs(pr4 + 2);
        float4 q3 = __ldcs(pr4 + 3);
        float4 x0 = ldh4(egoIn + (long long)__float_as_int(q0.y) * EMB + 4 * l);
        float4 x1 = ldh4(egoIn + (long long)__float_as_int(q0.w) * EMB + 4 * l);
        float4 x2 = ldh4(egoIn + (long long)__float_as_int(q1.y) * EMB + 4 * l);
        float4 x3 = ldh4(egoIn + (long long)__float_as_int(q1.w) * EMB + 4 * l);
        float4 x4 = ldh4(egoIn + (long long)__float_as_int(q2.y) * EMB + 4 * l);
        float4 x5 = ldh4(egoIn + (long long)__float_as_int(q2.w) * EMB + 4 * l);
        float4 x6 = ldh4(egoIn + (long long)__float_as_int(q3.y) * EMB + 4 * l);
        float4 x7 = ldh4(egoIn + (long long)__float_as_int(q3.w) * EMB + 4 * l);
        a.x += q0.x * x0.x; a.y += q0.x * x0.y; a.z += q0.x * x0.z; a.w += q0.x * x0.w;
        a.x += q0.z * x1.x; a.y += q0.z * x1.y; a.z += q0.z * x1.z; a.w += q0.z * x1.w;
        a.x += q1.x * x2.x; a.y += q1.x * x2.y; a.z += q1.x * x2.z; a.w += q1.x * x2.w;
        a.x += q1.z * x3.x; a.y += q1.z * x3.y; a.z += q1.z * x3.z; a.w += q1.z * x3.w;
        a.x += q2.x * x4.x; a.y += q2.x * x4.y; a.z += q2.x * x4.z; a.w += q2.x * x4.w;
        a.x += q2.z * x5.x; a.y += q2.z * x5.y; a.z += q2.z * x5.z; a.w += q2.z * x5.w;
        a.x += q3.x * x6.x; a.y += q3.x * x6.y; a.z += q3.x * x6.z; a.w += q3.x * x6.w;
        a.x += q3.z * x7.x; a.y += q3.z * x7.y; a.z += q3.z * x7.z; a.w += q3.z * x7.w;
    }
    for (; j < end; ++j) {
        float2 p = __ldcs(&g_pair[j]);
        float4 x = ldh4(egoIn + (long long)__float_as_int(p.y) * EMB + 4 * l);
        a.x += p.x * x.x; a.y += p.x * x.y; a.z += p.x * x.z; a.w += p.x * x.w;
    }

    // noise row-norm over 64 elems (16 lanes x 4), shfl reduce within half-warp
    float4 n = __ldcs(((const float4*)noise_k) + hw * 16 + l);   // streaming read
    float ss = n.x * n.x + n.y * n.y + n.z * n.z + n.w * n.w;
    ss += __shfl_xor_sync(0xffffffffu, ss, 8, 16);
    ss += __shfl_xor_sync(0xffffffffu, ss, 4, 16);
    ss += __shfl_xor_sync(0xffffffffu, ss, 2, 16);
    ss += __shfl_xor_sync(0xffffffffu, ss, 1, 16);
    float inv = EPS / fmaxf(sqrtf(ss), 1e-12f);

    float4 e;
    e.x = a.x + sgn(a.x) * n.x * inv;
    e.y = a.y + sgn(a.y) * n.y * inv;
    e.z = a.z + sgn(a.z) * n.z * inv;
    e.w = a.w + sgn(a.w) * n.w * inv;

    long long o = (long long)hw * EMB + 4 * l;              // element offset
    if (L == 0) {
        sth4(g_halfB + o, e);
    } else if (L == 1) {
        sth4(g_halfC + o, e);
    } else {
        // ego0 from the exact fp32 inputs; e1,e2 from the fp16 copies
        float4 z0;
        if (hw < USER_NUM) z0 = __ldcs((const float4*)(ue + o));
        else               z0 = __ldcs((const float4*)(ie + o - (long long)USER_NUM * EMB));
        float4 z1 = ldh4(g_halfB + o);
        float4 z2 = ldh4(g_halfC + o);
        float4 r = make_float4((z0.x + z1.x + z2.x + e.x) * 0.25f,
                               (z0.y + z1.y + z2.y + e.y) * 0.25f,
                               (z0.z + z1.z + z2.z + e.z) * 0.25f,
                               (z0.w + z1.w + z2.w + e.w) * 0.25f);
        __stcs((float4*)(out + o), r);                      // never re-read
    }
}

// ---------------------------------------------------------------------------
// launch
// Inputs: 0 user_emb, 1 item_emb, 2 adj_vals, 3 noise, 4 adj_rows, 5 adj_cols
// ---------------------------------------------------------------------------
extern "C" void kernel_launch(void* const* d_in, const int* in_sizes, int n_in,
                              void* d_out, int out_size) {
    const float* ue    = (const float*)d_in[0];
    const float* ie    = (const float*)d_in[1];
    const float* vals  = (const float*)d_in[2];
    const float* noise = (const float*)d_in[3];
    const int*   rows  = (const int*)d_in[4];
    const int*   cols  = (const int*)d_in[5];
    float* out = (float*)d_out;
    (void)in_sizes; (void)n_in; (void)out_size;

    const int nnz_blocks  = (NNZ + 255) / 256;              // covers NELEM/4 too
    const int row_blocks  = (NTOT + 255) / 256;
    const int lay_blocks  = (NTOT * 16 + 255) / 256;        // half-warp per row

    init_hist_kernel<<<nnz_blocks, 256>>>(ue, ie, rows);

    scan1_kernel<<<NBLK, 1024>>>();
    scan23_kernel<<<row_blocks, 256>>>();
    scatter_kernel<<<nnz_blocks, 256>>>(vals, rows, cols);

    // 3 fused layers: halfA -> halfB -> halfC -> averaged out
    layer_kernel<0><<<lay_blocks, 256>>>(noise + 0LL * NELEM, ue, ie, out);
    layer_kernel<1><<<lay_blocks, 256>>>(noise + 1LL * NELEM, ue, ie, out);
    layer_kernel<2><<<lay_blocks, 256>>>(noise + 2LL * NELEM, ue, ie, out);
}